// round 1
// baseline (speedup 1.0000x reference)
#include <cuda_runtime.h>

#define BATCH 8
#define SEQ   2048
#define DIM   64
#define BM    64
#define BN    64
#define ST    68   // padded row stride (floats): 68*4B = 272B, 16B-aligned, kills bank conflicts

// Dynamic smem layout (floats):
//   Qs[DIM][ST]  : Q tile transposed, Qs[d*ST+m]
//   KP[DIM][ST]  : K tile transposed Ks[d*ST+n]; reused as P tile Ps[m*ST+t]
//   Vs[BN][ST]   : V tile natural, Vs[n*ST+d]
//   q2[BM], k2[BN]
#define SMEM_FLOATS (3 * DIM * ST + BM + BN)
#define SMEM_BYTES  (SMEM_FLOATS * 4)

__global__ __launch_bounds__(256, 1)
void gauss_attn_kernel(const float* __restrict__ Q,
                       const float* __restrict__ Kg,
                       const float* __restrict__ V,
                       float* __restrict__ O)
{
    extern __shared__ float sm[];
    float* Qs = sm;                    // DIM*ST
    float* KP = Qs + DIM * ST;         // DIM*ST (K tile, then P tile)
    float* Vs = KP + DIM * ST;         // BN*ST
    float* q2 = Vs + BN * ST;          // BM
    float* k2 = q2 + BM;               // BN

    const int tid = threadIdx.x;
    const int tx  = tid & 15;          // 0..15  -> 4 cols each
    const int ty  = tid >> 4;          // 0..15  -> 4 rows each
    const int b   = blockIdx.y;
    const int m0  = blockIdx.x * BM;

    const float* Qb = Q  + (size_t)b * SEQ * DIM;
    const float* Kb = Kg + (size_t)b * SEQ * DIM;
    const float* Vb = V  + (size_t)b * SEQ * DIM;

    // ---- load Q tile (transposed into Qs[d][m]) ----
    #pragma unroll
    for (int idx = tid; idx < BM * DIM; idx += 256) {
        int m = idx >> 6;
        int d = idx & 63;
        Qs[d * ST + m] = Qb[(size_t)(m0 + m) * DIM + d];
    }
    __syncthreads();
    if (tid < BM) {
        float s = 0.f;
        #pragma unroll 8
        for (int d = 0; d < DIM; ++d) { float v = Qs[d * ST + tid]; s += v * v; }
        q2[tid] = s;
    }

    float oacc[4][4] = {};
    float rsum[4]    = {};

    for (int n0 = 0; n0 < SEQ; n0 += BN) {
        // guard: previous GEMM2 reads of KP/Vs done; also q2 ready on iter 0
        __syncthreads();

        // ---- load K tile (transposed) and V tile ----
        #pragma unroll
        for (int idx = tid; idx < BN * DIM; idx += 256) {
            int n = idx >> 6;
            int d = idx & 63;
            float kv = Kb[(size_t)(n0 + n) * DIM + d];
            float vv = Vb[(size_t)(n0 + n) * DIM + d];
            KP[d * ST + n] = kv;
            Vs[n * ST + d] = vv;
        }
        __syncthreads();
        if (tid < BN) {
            float s = 0.f;
            #pragma unroll 8
            for (int d = 0; d < DIM; ++d) { float v = KP[d * ST + tid]; s += v * v; }
            k2[tid] = s;
        }
        __syncthreads();

        // ---- GEMM1: acc[i][j] = sum_d Q[m,d]*K[n,d] ----
        float acc[4][4] = {};
        #pragma unroll 8
        for (int d = 0; d < DIM; ++d) {
            float4 a  = *(const float4*)&Qs[d * ST + ty * 4];
            float4 bb = *(const float4*)&KP[d * ST + tx * 4];
            acc[0][0] += a.x * bb.x; acc[0][1] += a.x * bb.y; acc[0][2] += a.x * bb.z; acc[0][3] += a.x * bb.w;
            acc[1][0] += a.y * bb.x; acc[1][1] += a.y * bb.y; acc[1][2] += a.y * bb.z; acc[1][3] += a.y * bb.w;
            acc[2][0] += a.z * bb.x; acc[2][1] += a.z * bb.y; acc[2][2] += a.z * bb.z; acc[2][3] += a.z * bb.w;
            acc[3][0] += a.w * bb.x; acc[3][1] += a.w * bb.y; acc[3][2] += a.w * bb.z; acc[3][3] += a.w * bb.w;
        }

        // ---- elementwise: p = exp(exp(-sqrt(max(q2+k2-2qk,0)))) ----
        float q2r[4], k2c[4];
        #pragma unroll
        for (int i = 0; i < 4; ++i) q2r[i] = q2[ty * 4 + i];
        #pragma unroll
        for (int j = 0; j < 4; ++j) k2c[j] = k2[tx * 4 + j];

        float p[4][4];
        #pragma unroll
        for (int i = 0; i < 4; ++i) {
            #pragma unroll
            for (int j = 0; j < 4; ++j) {
                float d2 = fmaxf(q2r[i] + k2c[j] - 2.f * acc[i][j], 0.f);
                float w  = __expf(-sqrtf(d2));   // w in (0,1] -> no max-sub needed
                float pe = __expf(w);
                p[i][j]  = pe;
                rsum[i] += pe;
            }
        }

        __syncthreads();  // all warps done reading K tile from KP

        // ---- write P[m][t] (conflict-free float4 rows) ----
        #pragma unroll
        for (int i = 0; i < 4; ++i) {
            *(float4*)&KP[(ty * 4 + i) * ST + tx * 4] =
                make_float4(p[i][0], p[i][1], p[i][2], p[i][3]);
        }
        __syncthreads();

        // ---- GEMM2: oacc[i][j] += sum_t P[m,t]*V[t,d] ----
        #pragma unroll 8
        for (int t = 0; t < BN; ++t) {
            float4 bb = *(const float4*)&Vs[t * ST + tx * 4];
            #pragma unroll
            for (int i = 0; i < 4; ++i) {
                float a = KP[(ty * 4 + i) * ST + t];   // broadcast within half-warp
                oacc[i][0] += a * bb.x;
                oacc[i][1] += a * bb.y;
                oacc[i][2] += a * bb.z;
                oacc[i][3] += a * bb.w;
            }
        }
    }

    // ---- reduce rowsum across the 16 tx-threads of each row, normalize, store ----
    #pragma unroll
    for (int i = 0; i < 4; ++i) {
        float r = rsum[i];
        r += __shfl_xor_sync(0xffffffffu, r, 1);
        r += __shfl_xor_sync(0xffffffffu, r, 2);
        r += __shfl_xor_sync(0xffffffffu, r, 4);
        r += __shfl_xor_sync(0xffffffffu, r, 8);
        float inv = 1.f / r;
        float4 o = make_float4(oacc[i][0] * inv, oacc[i][1] * inv,
                               oacc[i][2] * inv, oacc[i][3] * inv);
        *(float4*)&O[((size_t)b * SEQ + m0 + ty * 4 + i) * DIM + tx * 4] = o;
    }
}

extern "C" void kernel_launch(void* const* d_in, const int* in_sizes, int n_in,
                              void* d_out, int out_size)
{
    const float* Q = (const float*)d_in[0];
    const float* K = (const float*)d_in[1];
    const float* V = (const float*)d_in[2];
    float* O = (float*)d_out;

    cudaFuncSetAttribute(gauss_attn_kernel,
                         cudaFuncAttributeMaxDynamicSharedMemorySize, SMEM_BYTES);

    dim3 grid(SEQ / BM, BATCH);   // 32 x 8 = 256 CTAs
    gauss_attn_kernel<<<grid, 256, SMEM_BYTES>>>(Q, K, V, O);
}

// round 3
// speedup vs baseline: 3.0850x; 3.0850x over previous
#include <cuda_runtime.h>
#include <cstdint>

#define SEQ 2048
#define DIM 64
#define BM  128
#define TN  128
#define NT  (SEQ / TN)

// smem layout (bytes)
#define SM_Q    0        // 128 x 128B bf16, SW128
#define SM_KB   16384    // K tile bf16
#define SM_VB   32768    // V tile bf16
#define SM_K2   49152    // 128 f32
#define SM_Q2   49664    // 128 f32
#define SM_RS   50176    // 2*128 f32
#define SM_SVR  51200    // 256*4 f32
#define SM_SVS  55296    // 64 f32
#define SM_OB   16384    // reuse K/V region after main loop
#define OB_ST   66       // padded f32 stride for O exchange
#define SMEM_BYTES 55552

#define SW128(o) ((o) ^ (((o) >> 3) & 0x70))

__device__ __forceinline__ uint32_t smem_u32(const void* p) {
    uint32_t a;
    asm("{ .reg .u64 t; cvta.to.shared.u64 t, %1; cvt.u32.u64 %0, t; }" : "=r"(a) : "l"(p));
    return a;
}
__device__ __forceinline__ void ldm_x4(uint32_t a, uint32_t r[4]) {
    asm volatile("ldmatrix.sync.aligned.m8n8.x4.shared.b16 {%0,%1,%2,%3}, [%4];"
                 : "=r"(r[0]), "=r"(r[1]), "=r"(r[2]), "=r"(r[3]) : "r"(a));
}
__device__ __forceinline__ void ldm_x4_t(uint32_t a, uint32_t r[4]) {
    asm volatile("ldmatrix.sync.aligned.m8n8.x4.trans.shared.b16 {%0,%1,%2,%3}, [%4];"
                 : "=r"(r[0]), "=r"(r[1]), "=r"(r[2]), "=r"(r[3]) : "r"(a));
}
__device__ __forceinline__ void mma_bf16(float* c, const uint32_t* a, uint32_t b0, uint32_t b1) {
    asm volatile("mma.sync.aligned.m16n8k16.row.col.f32.bf16.bf16.f32 "
                 "{%0,%1,%2,%3}, {%4,%5,%6,%7}, {%8,%9}, {%0,%1,%2,%3};"
                 : "+f"(c[0]), "+f"(c[1]), "+f"(c[2]), "+f"(c[3])
                 : "r"(a[0]), "r"(a[1]), "r"(a[2]), "r"(a[3]), "r"(b0), "r"(b1));
}
// res = {lo(low 16), hi(high 16)} as bf16x2
#define CVT_BF16X2(res, lo, hi) \
    asm("cvt.rn.bf16x2.f32 %0, %1, %2;" : "=r"(res) : "f"(hi), "f"(lo))

__device__ __forceinline__ float sqrt_approx(float x) {
    float r; asm("sqrt.approx.f32 %0, %1;" : "=f"(r) : "f"(x)); return r;
}

__global__ __launch_bounds__(256, 1)
void gauss_attn_mma(const float* __restrict__ Q,
                    const float* __restrict__ Kg,
                    const float* __restrict__ V,
                    float* __restrict__ O)
{
    extern __shared__ char smc[];
    const uint32_t sb = smem_u32(smc);
    float* k2s = (float*)(smc + SM_K2);
    float* q2s = (float*)(smc + SM_Q2);
    float* rsS = (float*)(smc + SM_RS);
    float* svr = (float*)(smc + SM_SVR);
    float* svS = (float*)(smc + SM_SVS);
    float* obf = (float*)(smc + SM_OB);

    const int tid  = threadIdx.x;
    const int lane = tid & 31;
    const int wid  = tid >> 5;
    const int wm   = wid & 3;    // m-block (32 rows)
    const int wn   = wid >> 2;   // n-half (64 keys)
    const int g    = lane >> 2;
    const int b    = blockIdx.y;
    const int m0   = blockIdx.x * BM;

    const float* Qb = Q  + ((size_t)b * SEQ + m0) * DIM;
    const float* Kb = Kg + (size_t)b * SEQ * DIM;
    const float* Vb = V  + (size_t)b * SEQ * DIM;

    // ---- prologue: Q -> smem bf16 (SW128) + q2 ----
    #pragma unroll
    for (int i = 0; i < 8; ++i) {
        int idx = i * 256 + tid;
        int r = idx >> 4, c = idx & 15;
        float4 v = *(const float4*)(Qb + r * 64 + c * 4);
        uint32_t p0, p1;
        CVT_BF16X2(p0, v.x, v.y);
        CVT_BF16X2(p1, v.z, v.w);
        *(uint2*)(smc + SM_Q + SW128(r * 128 + c * 8)) = make_uint2(p0, p1);
    }
    if (tid < 128) {
        const float4* qr = (const float4*)(Qb + tid * 64);
        float s = 0.f;
        #pragma unroll
        for (int i = 0; i < 16; ++i) {
            float4 v = qr[i];
            s += v.x * v.x + v.y * v.y + v.z * v.z + v.w * v.w;
        }
        q2s[tid] = s;
    }
    __syncthreads();

    float q2v[4];
    #pragma unroll
    for (int mi = 0; mi < 2; ++mi)
        #pragma unroll
        for (int r = 0; r < 2; ++r)
            q2v[mi * 2 + r] = q2s[wm * 32 + mi * 16 + g + r * 8];

    float oacc[2][8][4] = {};   // [mi][dj][frag]
    float rs[4] = {};
    float sv[4] = {};

    for (int it = 0; it < NT; ++it) {
        const float* Kt = Kb + (size_t)it * TN * DIM;
        const float* Vt = Vb + (size_t)it * TN * DIM;
        __syncthreads();
        // ---- K,V tiles -> smem bf16 (row-major, SW128); accumulate sum(V) ----
        #pragma unroll
        for (int i = 0; i < 8; ++i) {
            int idx = i * 256 + tid;
            int t = idx >> 4, c = idx & 15;
            float4 kv = *(const float4*)(Kt + t * 64 + c * 4);
            float4 vv = *(const float4*)(Vt + t * 64 + c * 4);
            uint32_t p0, p1;
            CVT_BF16X2(p0, kv.x, kv.y);
            CVT_BF16X2(p1, kv.z, kv.w);
            *(uint2*)(smc + SM_KB + SW128(t * 128 + c * 8)) = make_uint2(p0, p1);
            CVT_BF16X2(p0, vv.x, vv.y);
            CVT_BF16X2(p1, vv.z, vv.w);
            *(uint2*)(smc + SM_VB + SW128(t * 128 + c * 8)) = make_uint2(p0, p1);
            sv[0] += vv.x; sv[1] += vv.y; sv[2] += vv.z; sv[3] += vv.w;
        }
        if (tid < 128) {
            const float4* kr = (const float4*)(Kt + tid * 64);
            float s = 0.f;
            #pragma unroll
            for (int i = 0; i < 16; ++i) {
                float4 v = kr[i];
                s += v.x * v.x + v.y * v.y + v.z * v.z + v.w * v.w;
            }
            k2s[tid] = s;
        }
        __syncthreads();

        #pragma unroll
        for (int np = 0; np < 4; ++np) {
            const int tloc = wn * 64 + np * 16;  // this warp's 16-key group

            // ---- GEMM1: S[32 x 16] for this group ----
            float sacc[2][2][4] = {};
            #pragma unroll
            for (int kk = 0; kk < 4; ++kk) {
                uint32_t bK[4];
                uint32_t ka = sb + SM_KB + SW128(
                    (tloc + (lane & 7) + ((lane >> 4) & 1) * 8) * 128
                    + kk * 32 + ((lane >> 3) & 1) * 16);
                ldm_x4(ka, bK);
                #pragma unroll
                for (int mi = 0; mi < 2; ++mi) {
                    uint32_t aQ[4];
                    uint32_t qa = sb + SM_Q + SW128(
                        (wm * 32 + mi * 16 + (lane & 7) + ((lane >> 3) & 1) * 8) * 128
                        + kk * 32 + ((lane >> 4) & 1) * 16);
                    ldm_x4(qa, aQ);
                    mma_bf16(sacc[mi][0], aQ, bK[0], bK[1]);
                    mma_bf16(sacc[mi][1], aQ, bK[2], bK[3]);
                }
            }

            // ---- epilogue: w' = expm1(exp(-sqrt(d2))) -> A frags (bf16) ----
            uint32_t aP[2][4];
            #pragma unroll
            for (int mi = 0; mi < 2; ++mi) {
                #pragma unroll
                for (int njp = 0; njp < 2; ++njp) {
                    int tcol = tloc + njp * 8 + 2 * (lane & 3);
                    float2 kk2 = *(const float2*)&k2s[tcol];
                    float wpr[4];
                    #pragma unroll
                    for (int e = 0; e < 4; ++e) {
                        float qk = sacc[mi][njp][e];
                        float bsum = q2v[mi * 2 + (e >> 1)] + ((e & 1) ? kk2.y : kk2.x);
                        float d2 = fmaxf(fmaf(-2.f, qk, bsum), 0.f);
                        float w = __expf(-sqrt_approx(d2));
                        float t3 = fmaf(w, 0.16666667f, 0.5f);
                        t3 = fmaf(w, t3, 1.0f);
                        float wp = w * t3;            // expm1(w)
                        wpr[e] = wp;
                        rs[mi * 2 + (e >> 1)] += wp;
                    }
                    CVT_BF16X2(aP[mi][njp * 2 + 0], wpr[0], wpr[1]);
                    CVT_BF16X2(aP[mi][njp * 2 + 1], wpr[2], wpr[3]);
                }
            }

            // ---- GEMM2: O[32 x 64] += P[32 x 16] * V[16 x 64] ----
            #pragma unroll
            for (int dg = 0; dg < 4; ++dg) {
                uint32_t bV[4];
                uint32_t va = sb + SM_VB + SW128(
                    (tloc + (lane & 7) + ((lane >> 3) & 1) * 8) * 128
                    + dg * 32 + ((lane >> 4) & 1) * 16);
                ldm_x4_t(va, bV);
                #pragma unroll
                for (int mi = 0; mi < 2; ++mi) {
                    mma_bf16(oacc[mi][dg * 2 + 0], aP[mi], bV[0], bV[1]);
                    mma_bf16(oacc[mi][dg * 2 + 1], aP[mi], bV[2], bV[3]);
                }
            }
        }
    }

    // ================= finalization =================
    __syncthreads();

    // sum(V) partials and rowsums
    ((float4*)svr)[tid] = make_float4(sv[0], sv[1], sv[2], sv[3]);
    #pragma unroll
    for (int j = 0; j < 4; ++j) {
        rs[j] += __shfl_xor_sync(0xffffffffu, rs[j], 1);
        rs[j] += __shfl_xor_sync(0xffffffffu, rs[j], 2);
    }
    if ((lane & 3) == 0) {
        #pragma unroll
        for (int j = 0; j < 4; ++j) {
            int row = wm * 32 + (j >> 1) * 16 + g + (j & 1) * 8;
            rsS[wn * 128 + row] = rs[j];
        }
    }
    // wn=0 warps park their O partials in smem
    if (wn == 0) {
        #pragma unroll
        for (int mi = 0; mi < 2; ++mi) {
            #pragma unroll
            for (int dj = 0; dj < 8; ++dj) {
                int row0 = wm * 32 + mi * 16 + g;
                int col = dj * 8 + 2 * (lane & 3);
                *(float2*)&obf[row0 * OB_ST + col] =
                    make_float2(oacc[mi][dj][0], oacc[mi][dj][1]);
                *(float2*)&obf[(row0 + 8) * OB_ST + col] =
                    make_float2(oacc[mi][dj][2], oacc[mi][dj][3]);
            }
        }
    }
    __syncthreads();

    if (tid < 64) {
        int dcc = tid >> 2, k = tid & 3;
        float s = 0.f;
        #pragma unroll
        for (int gg = 0; gg < 16; ++gg) s += svr[(dcc + 16 * gg) * 4 + k];
        svS[tid] = s;
    }
    __syncthreads();

    // wn=1 warps combine and write out
    if (wn == 1) {
        float inv[4];
        #pragma unroll
        for (int j = 0; j < 4; ++j) {
            int row = wm * 32 + (j >> 1) * 16 + g + (j & 1) * 8;
            inv[j] = 1.f / (2048.f + rsS[row] + rsS[128 + row]);
        }
        #pragma unroll
        for (int mi = 0; mi < 2; ++mi) {
            #pragma unroll
            for (int dj = 0; dj < 8; ++dj) {
                int row0 = wm * 32 + mi * 16 + g;
                int col = dj * 8 + 2 * (lane & 3);
                float2 svp = *(const float2*)&svS[col];
                float2 o0 = *(const float2*)&obf[row0 * OB_ST + col];
                float2 o1 = *(const float2*)&obf[(row0 + 8) * OB_ST + col];
                float iv0 = inv[mi * 2], iv1 = inv[mi * 2 + 1];
                float2 r0 = make_float2((oacc[mi][dj][0] + o0.x + svp.x) * iv0,
                                        (oacc[mi][dj][1] + o0.y + svp.y) * iv0);
                float2 r1 = make_float2((oacc[mi][dj][2] + o1.x + svp.x) * iv1,
                                        (oacc[mi][dj][3] + o1.y + svp.y) * iv1);
                *(float2*)&O[((size_t)b * SEQ + m0 + row0) * DIM + col] = r0;
                *(float2*)&O[((size_t)b * SEQ + m0 + row0 + 8) * DIM + col] = r1;
            }
        }
    }
}

extern "C" void kernel_launch(void* const* d_in, const int* in_sizes, int n_in,
                              void* d_out, int out_size)
{
    const float* Q = (const float*)d_in[0];
    const float* K = (const float*)d_in[1];
    const float* V = (const float*)d_in[2];
    float* O = (float*)d_out;

    cudaFuncSetAttribute(gauss_attn_mma,
                         cudaFuncAttributeMaxDynamicSharedMemorySize, SMEM_BYTES);
    dim3 grid(SEQ / BM, 8);   // 16 x 8 = 128 CTAs, single wave
    gauss_attn_mma<<<grid, 256, SMEM_BYTES>>>(Q, K, V, O);
}

// round 4
// speedup vs baseline: 5.9449x; 1.9270x over previous
#include <cuda_runtime.h>
#include <cstdint>

#define SEQ 2048
#define DIM 64
#define BM  128
#define TN  128
#define NT  (SEQ / TN)

// smem layout (bytes)
#define SM_Q    0        // 128 rows x 128B bf16, SW128
#define SM_KB   16384
#define SM_VB   32768
#define SM_K2   49152    // 128 f32
#define SM_Q2   49664    // 128 f32
#define SM_RS   50176    // 2*128 f32
#define SM_SVR  51200    // 512*4 f32 (8192 B)
#define SM_SVS  59392    // 64 f32
#define SM_OB   0        // reuse Q/K region after main loop (128 x 66 f32)
#define OB_ST   66
#define SMEM_BYTES 59648

#define SW128(o) ((o) ^ (((o) >> 3) & 0x70))

__device__ __forceinline__ uint32_t smem_u32(const void* p) {
    uint32_t a;
    asm("{ .reg .u64 t; cvta.to.shared.u64 t, %1; cvt.u32.u64 %0, t; }" : "=r"(a) : "l"(p));
    return a;
}
__device__ __forceinline__ void ldm_x4(uint32_t a, uint32_t r[4]) {
    asm volatile("ldmatrix.sync.aligned.m8n8.x4.shared.b16 {%0,%1,%2,%3}, [%4];"
                 : "=r"(r[0]), "=r"(r[1]), "=r"(r[2]), "=r"(r[3]) : "r"(a));
}
__device__ __forceinline__ void ldm_x4_t(uint32_t a, uint32_t r[4]) {
    asm volatile("ldmatrix.sync.aligned.m8n8.x4.trans.shared.b16 {%0,%1,%2,%3}, [%4];"
                 : "=r"(r[0]), "=r"(r[1]), "=r"(r[2]), "=r"(r[3]) : "r"(a));
}
__device__ __forceinline__ void mma_bf16(float* c, const uint32_t* a, uint32_t b0, uint32_t b1) {
    asm volatile("mma.sync.aligned.m16n8k16.row.col.f32.bf16.bf16.f32 "
                 "{%0,%1,%2,%3}, {%4,%5,%6,%7}, {%8,%9}, {%0,%1,%2,%3};"
                 : "+f"(c[0]), "+f"(c[1]), "+f"(c[2]), "+f"(c[3])
                 : "r"(a[0]), "r"(a[1]), "r"(a[2]), "r"(a[3]), "r"(b0), "r"(b1));
}
#define CVT_BF16X2(res, lo, hi) \
    asm("cvt.rn.bf16x2.f32 %0, %1, %2;" : "=r"(res) : "f"(hi), "f"(lo))

__device__ __forceinline__ float sqrt_approx(float x) {
    float r; asm("sqrt.approx.f32 %0, %1;" : "=f"(r) : "f"(x)); return r;
}

__global__ __launch_bounds__(512, 1)
void gauss_attn_mma(const float* __restrict__ Q,
                    const float* __restrict__ Kg,
                    const float* __restrict__ V,
                    float* __restrict__ O)
{
    extern __shared__ char smc[];
    const uint32_t sb = smem_u32(smc);
    float* k2s = (float*)(smc + SM_K2);
    float* q2s = (float*)(smc + SM_Q2);
    float* rsS = (float*)(smc + SM_RS);
    float* svr = (float*)(smc + SM_SVR);
    float* svS = (float*)(smc + SM_SVS);
    float* obf = (float*)(smc + SM_OB);

    const int tid  = threadIdx.x;
    const int lane = tid & 31;
    const int wid  = tid >> 5;
    const int wm   = wid & 7;    // m-block: 16 rows
    const int wn   = wid >> 3;   // n-half: 64 keys
    const int g    = lane >> 2;
    const int b    = blockIdx.y;
    const int m0   = blockIdx.x * BM;

    const float* Qb = Q  + ((size_t)b * SEQ + m0) * DIM;
    const float* Kb = Kg + (size_t)b * SEQ * DIM;
    const float* Vb = V  + (size_t)b * SEQ * DIM;

    // ---- prologue: Q -> smem bf16 (SW128) ----
    #pragma unroll
    for (int i = 0; i < 4; ++i) {
        int idx = i * 512 + tid;
        int r = idx >> 4, c = idx & 15;
        float4 v = *(const float4*)(Qb + r * 64 + c * 4);
        uint32_t p0, p1;
        CVT_BF16X2(p0, v.x, v.y);
        CVT_BF16X2(p1, v.z, v.w);
        *(uint2*)(smc + SM_Q + SW128(r * 128 + c * 8)) = make_uint2(p0, p1);
    }
    // q2 (quad per row + shfl)
    {
        int row = tid >> 2, part = tid & 3;
        const float4* qr = (const float4*)(Qb + row * 64 + part * 16);
        float s = 0.f;
        #pragma unroll
        for (int j = 0; j < 4; ++j) {
            float4 v = qr[j];
            s += v.x * v.x + v.y * v.y + v.z * v.z + v.w * v.w;
        }
        s += __shfl_xor_sync(0xffffffffu, s, 1);
        s += __shfl_xor_sync(0xffffffffu, s, 2);
        if (part == 0) q2s[row] = s;
    }
    __syncthreads();

    // ---- hoist Q fragments (constant for whole kernel) ----
    uint32_t aQ[4][4];
    #pragma unroll
    for (int kk = 0; kk < 4; ++kk) {
        uint32_t qa = sb + SM_Q + SW128(
            (wm * 16 + (lane & 7) + ((lane >> 3) & 1) * 8) * 128
            + kk * 32 + ((lane >> 4) & 1) * 16);
        ldm_x4(qa, aQ[kk]);
    }
    float q2v0 = q2s[wm * 16 + g];
    float q2v1 = q2s[wm * 16 + g + 8];

    // precomputed swizzled ldmatrix bases (np advances by +2048, swizzle-invariant)
    uint32_t kaddr[4], vaddr[4];
    #pragma unroll
    for (int kk = 0; kk < 4; ++kk)
        kaddr[kk] = sb + SM_KB + SW128(
            (wn * 64 + (lane & 7) + ((lane >> 4) & 1) * 8) * 128
            + kk * 32 + ((lane >> 3) & 1) * 16);
    #pragma unroll
    for (int dg = 0; dg < 4; ++dg)
        vaddr[dg] = sb + SM_VB + SW128(
            (wn * 64 + (lane & 7) + ((lane >> 3) & 1) * 8) * 128
            + dg * 32 + ((lane >> 4) & 1) * 16);

    float oacc[8][4] = {};
    float rs0 = 0.f, rs1 = 0.f;
    float sv[4] = {};

    for (int it = 0; it < NT; ++it) {
        const float* Kt = Kb + (size_t)it * TN * DIM;
        const float* Vt = Vb + (size_t)it * TN * DIM;
        __syncthreads();
        // ---- K,V tiles -> smem bf16 (SW128); accumulate sum(V) ----
        #pragma unroll
        for (int i = 0; i < 4; ++i) {
            int idx = i * 512 + tid;
            int t = idx >> 4, c = idx & 15;
            float4 kv = *(const float4*)(Kt + t * 64 + c * 4);
            float4 vv = *(const float4*)(Vt + t * 64 + c * 4);
            uint32_t p0, p1;
            CVT_BF16X2(p0, kv.x, kv.y);
            CVT_BF16X2(p1, kv.z, kv.w);
            *(uint2*)(smc + SM_KB + SW128(t * 128 + c * 8)) = make_uint2(p0, p1);
            CVT_BF16X2(p0, vv.x, vv.y);
            CVT_BF16X2(p1, vv.z, vv.w);
            *(uint2*)(smc + SM_VB + SW128(t * 128 + c * 8)) = make_uint2(p0, p1);
            sv[0] += vv.x; sv[1] += vv.y; sv[2] += vv.z; sv[3] += vv.w;
        }
        // k2
        {
            int row = tid >> 2, part = tid & 3;
            const float4* kr = (const float4*)(Kt + row * 64 + part * 16);
            float s = 0.f;
            #pragma unroll
            for (int j = 0; j < 4; ++j) {
                float4 v = kr[j];
                s += v.x * v.x + v.y * v.y + v.z * v.z + v.w * v.w;
            }
            s += __shfl_xor_sync(0xffffffffu, s, 1);
            s += __shfl_xor_sync(0xffffffffu, s, 2);
            if (part == 0) k2s[row] = s;
        }
        __syncthreads();

        #pragma unroll
        for (int np = 0; np < 4; ++np) {
            const int tloc = wn * 64 + np * 16;
            const uint32_t npo = np * 2048;

            // ---- GEMM1: S[16 x 16] ----
            float sacc[2][4] = {};
            #pragma unroll
            for (int kk = 0; kk < 4; ++kk) {
                uint32_t bK[4];
                ldm_x4(kaddr[kk] + npo, bK);
                mma_bf16(sacc[0], aQ[kk], bK[0], bK[1]);
                mma_bf16(sacc[1], aQ[kk], bK[2], bK[3]);
            }

            // ---- epilogue: w' = expm1(exp(-sqrt(d2))) -> A frag ----
            uint32_t aP[4];
            #pragma unroll
            for (int njp = 0; njp < 2; ++njp) {
                int tcol = tloc + njp * 8 + 2 * (lane & 3);
                float2 kk2 = *(const float2*)&k2s[tcol];
                float wpr[4];
                #pragma unroll
                for (int e = 0; e < 4; ++e) {
                    float qk = sacc[njp][e];
                    float bsum = ((e >> 1) ? q2v1 : q2v0) + ((e & 1) ? kk2.y : kk2.x);
                    float d2 = fmaxf(fmaf(-2.f, qk, bsum), 0.f);
                    float w = __expf(-sqrt_approx(d2));
                    float t3 = fmaf(w, 0.16666667f, 0.5f);
                    t3 = fmaf(w, t3, 1.0f);
                    float wp = w * t3;            // expm1(w)
                    wpr[e] = wp;
                    if (e >> 1) rs1 += wp; else rs0 += wp;
                }
                CVT_BF16X2(aP[njp * 2 + 0], wpr[0], wpr[1]);
                CVT_BF16X2(aP[njp * 2 + 1], wpr[2], wpr[3]);
            }

            // ---- GEMM2: O[16 x 64] += P[16 x 16] * V[16 x 64] ----
            #pragma unroll
            for (int dg = 0; dg < 4; ++dg) {
                uint32_t bV[4];
                ldm_x4_t(vaddr[dg] + npo, bV);
                mma_bf16(oacc[dg * 2 + 0], aP, bV[0], bV[1]);
                mma_bf16(oacc[dg * 2 + 1], aP, bV[2], bV[3]);
            }
        }
    }

    // ================= finalization =================
    __syncthreads();

    ((float4*)svr)[tid] = make_float4(sv[0], sv[1], sv[2], sv[3]);
    rs0 += __shfl_xor_sync(0xffffffffu, rs0, 1);
    rs0 += __shfl_xor_sync(0xffffffffu, rs0, 2);
    rs1 += __shfl_xor_sync(0xffffffffu, rs1, 1);
    rs1 += __shfl_xor_sync(0xffffffffu, rs1, 2);
    if ((lane & 3) == 0) {
        rsS[wn * 128 + wm * 16 + g]     = rs0;
        rsS[wn * 128 + wm * 16 + g + 8] = rs1;
    }
    // wn=0 parks O partials (obf reuses Q/K smem, dead now)
    if (wn == 0) {
        int row0 = wm * 16 + g;
        #pragma unroll
        for (int dj = 0; dj < 8; ++dj) {
            int col = dj * 8 + 2 * (lane & 3);
            *(float2*)&obf[row0 * OB_ST + col] = make_float2(oacc[dj][0], oacc[dj][1]);
            *(float2*)&obf[(row0 + 8) * OB_ST + col] = make_float2(oacc[dj][2], oacc[dj][3]);
        }
    }
    __syncthreads();

    if (tid < 64) {
        int cg = tid >> 2, k = tid & 3;
        float s = 0.f;
        #pragma unroll
        for (int j = 0; j < 32; ++j) s += svr[(cg + 16 * j) * 4 + k];
        svS[tid] = s;
    }
    __syncthreads();

    if (wn == 1) {
        int row0 = wm * 16 + g;
        float inv0 = 1.f / (2048.f + rsS[row0] + rsS[128 + row0]);
        float inv1 = 1.f / (2048.f + rsS[row0 + 8] + rsS[128 + row0 + 8]);
        #pragma unroll
        for (int dj = 0; dj < 8; ++dj) {
            int col = dj * 8 + 2 * (lane & 3);
            float2 svp = *(const float2*)&svS[col];
            float2 o0 = *(const float2*)&obf[row0 * OB_ST + col];
            float2 o1 = *(const float2*)&obf[(row0 + 8) * OB_ST + col];
            float2 r0 = make_float2((oacc[dj][0] + o0.x + svp.x) * inv0,
                                    (oacc[dj][1] + o0.y + svp.y) * inv0);
            float2 r1 = make_float2((oacc[dj][2] + o1.x + svp.x) * inv1,
                                    (oacc[dj][3] + o1.y + svp.y) * inv1);
            *(float2*)&O[((size_t)b * SEQ + m0 + row0) * DIM + col] = r0;
            *(float2*)&O[((size_t)b * SEQ + m0 + row0 + 8) * DIM + col] = r1;
        }
    }
}

extern "C" void kernel_launch(void* const* d_in, const int* in_sizes, int n_in,
                              void* d_out, int out_size)
{
    const float* Q = (const float*)d_in[0];
    const float* K = (const float*)d_in[1];
    const float* V = (const float*)d_in[2];
    float* O = (float*)d_out;

    cudaFuncSetAttribute(gauss_attn_mma,
                         cudaFuncAttributeMaxDynamicSharedMemorySize, SMEM_BYTES);
    dim3 grid(SEQ / BM, 8);   // 16 x 8 = 128 CTAs
    gauss_attn_mma<<<grid, 512, SMEM_BYTES>>>(Q, K, V, O);
}